// round 13
// baseline (speedup 1.0000x reference)
#include <cuda_runtime.h>
#include <cuda_fp16.h>
#include <cstdint>

// ---------------------------------------------------------------------------
// Problem constants
// ---------------------------------------------------------------------------
#define NTOK 8192
#define INF  1024
#define OUTF 1024
#define GS   8
#define KDIM (INF * 9)          // 9216 = silu + 8 laplacian features

static __device__ __align__(256) __half g_phi[(size_t)NTOK * KDIM];   // 151 MB
static __device__ __align__(256) __half g_w[(size_t)OUTF * KDIM];     // 18.9 MB

// ---------------------------------------------------------------------------
// prep_w (CLOCK CANARY: ~13.5us fast-DVFS / ~20.5us slow-DVFS)
// ---------------------------------------------------------------------------
__global__ void prep_w_kernel(const float* __restrict__ bw,
                              const float* __restrict__ sw,
                              const float* __restrict__ sc) {
    int idx = blockIdx.x * blockDim.x + threadIdx.x;
    if (idx >= OUTF * INF) return;
    int o = idx / INF;
    int i = idx - o * INF;
    size_t base = (size_t)o * KDIM + i;
    float scaler = sc[idx];
    g_w[base] = __float2half(bw[idx]);
    #pragma unroll
    for (int g = 0; g < GS; g++)
        g_w[base + (size_t)(1 + g) * INF] = __float2half(sw[(size_t)idx * GS + g] * scaler);
}

// ---------------------------------------------------------------------------
// prep_phi v3 (proven): 4 i per thread, 8-byte stores, MUFU-free poly exp2.
// ---------------------------------------------------------------------------
__device__ __forceinline__ void exp_pm(float xv, float& E, float& R) {
    const float L2E = 1.4426950408889634f;
    float s = xv * L2E;
    float k = s + 12582912.0f;
    int   n = __float_as_int(k) - 0x4B400000;
    float f = s - (k - 12582912.0f);
    float p = 1.33335581e-3f;
    p = fmaf(p, f, 9.61812910e-3f);
    p = fmaf(p, f, 5.55041087e-2f);
    p = fmaf(p, f, 2.40226507e-1f);
    p = fmaf(p, f, 6.93147181e-1f);
    p = fmaf(p, f, 1.0f);
    float nf = -f;
    float q = 1.33335581e-3f;
    q = fmaf(q, nf, 9.61812910e-3f);
    q = fmaf(q, nf, 5.55041087e-2f);
    q = fmaf(q, nf, 2.40226507e-1f);
    q = fmaf(q, nf, 6.93147181e-1f);
    q = fmaf(q, nf, 1.0f);
    E = p * __int_as_float((127 + n) << 23);
    R = q * __int_as_float((127 - n) << 23);
}

__device__ __forceinline__ float fast_sigmoid_from_R(float R) {
    float d = 1.0f + R;
    float y = __int_as_float(0x7EF477D5 - __float_as_int(d));
    y = y * (2.0f - d * y);
    y = y * (2.0f - d * y);
    y = y * (2.0f - d * y);
    return y;
}

__device__ __forceinline__ uint32_t pack2(float a, float b) {
    __half2 h = __floats2half2_rn(a, b);
    return *reinterpret_cast<uint32_t*>(&h);
}

__global__ void __launch_bounds__(256) prep_phi3_kernel(const float* __restrict__ x,
                                                        const float* __restrict__ gridp) {
    const int tid = threadIdx.x;
    const int i0 = tid * 4;
    const int n0 = blockIdx.x * 16;

    float cEv[4][GS], cRv[4][GS];
    #pragma unroll
    for (int e = 0; e < 4; e++)
        #pragma unroll
        for (int g = 0; g < GS; g++) {
            float gv = gridp[(i0 + e) * GS + g];
            cEv[e][g] = __expf(-gv);
            cRv[e][g] = __expf(gv);
        }

    for (int n = n0; n < n0 + 16; n++) {
        float4 xv = *reinterpret_cast<const float4*>(x + (size_t)n * INF + i0);
        float xa[4] = {xv.x, xv.y, xv.z, xv.w};
        float E[4], R[4], sil[4];
        #pragma unroll
        for (int e = 0; e < 4; e++) {
            exp_pm(xa[e], E[e], R[e]);
            sil[e] = xa[e] * fast_sigmoid_from_R(R[e]);
        }
        __half* base = g_phi + (size_t)n * KDIM + i0;
        uint2 u;
        u.x = pack2(sil[0], sil[1]);
        u.y = pack2(sil[2], sil[3]);
        *reinterpret_cast<uint2*>(base) = u;
        #pragma unroll
        for (int g = 0; g < GS; g++) {
            float v0 = fminf(E[0] * cEv[0][g], R[0] * cRv[0][g]);
            float v1 = fminf(E[1] * cEv[1][g], R[1] * cRv[1][g]);
            float v2 = fminf(E[2] * cEv[2][g], R[2] * cRv[2][g]);
            float v3 = fminf(E[3] * cEv[3][g], R[3] * cRv[3][g]);
            uint2 v;
            v.x = pack2(v0, v1);
            v.y = pack2(v2, v3);
            *reinterpret_cast<uint2*>(base + (size_t)(1 + g) * INF) = v;
        }
    }
}

// ---------------------------------------------------------------------------
// fp16 GEMM v7: 512 threads / 16 warps (4 per SMSP), CTA 128x256x64h,
// warps 4m x 4n (warp tile 32x64), 4-stage cp.async (192 KB, 1 CTA/SM).
// B fragments DOUBLE-BUFFERED (overlaps 2/3 of crossbar traffic with MMA);
// A fragments single-buffered, reloaded after each MMA burst.
// Register ledger: acc 64 + B-frags 32 + A-frags 8 + addr ~24 = 128 (no spill).
// ---------------------------------------------------------------------------
#define BM 128
#define BN 256
#define BKH 64
#define STAGES 4
#define A_BYTES (BM * 128)                 // 16 KB
#define B_BYTES (BN * 128)                 // 32 KB
#define STAGE_BYTES (A_BYTES + B_BYTES)    // 48 KB
#define SMEM_BYTES (STAGES * STAGE_BYTES)  // 192 KB
#define KT (KDIM / BKH)                    // 144

__device__ __forceinline__ void cp_async16(uint32_t smem_addr, const void* gptr) {
    asm volatile("cp.async.cg.shared.global [%0], [%1], 16;\n" :: "r"(smem_addr), "l"(gptr));
}
__device__ __forceinline__ uint32_t smem_u32(const void* p) {
    uint32_t a;
    asm("{ .reg .u64 t; cvta.to.shared.u64 t, %1; cvt.u32.u64 %0, t; }" : "=r"(a) : "l"(p));
    return a;
}
__device__ __forceinline__ void ldsm4(uint32_t r[4], uint32_t addr) {
    asm volatile("ldmatrix.sync.aligned.m8n8.x4.shared.b16 {%0,%1,%2,%3}, [%4];"
                 : "=r"(r[0]), "=r"(r[1]), "=r"(r[2]), "=r"(r[3]) : "r"(addr));
}
__device__ __forceinline__ void mma_f16(float c[4], const uint32_t a[4],
                                        uint32_t b0, uint32_t b1) {
    asm volatile(
        "mma.sync.aligned.m16n8k16.row.col.f32.f16.f16.f32 "
        "{%0,%1,%2,%3}, {%4,%5,%6,%7}, {%8,%9}, {%0,%1,%2,%3};\n"
        : "+f"(c[0]), "+f"(c[1]), "+f"(c[2]), "+f"(c[3])
        : "r"(a[0]), "r"(a[1]), "r"(a[2]), "r"(a[3]), "r"(b0), "r"(b1));
}
__device__ __forceinline__ uint32_t swz(int row, int chunk) {
    return (uint32_t)(row * 128 + ((chunk ^ (row & 7)) << 4));
}

__global__ void __launch_bounds__(512, 1) gemm_f16_kernel(float* __restrict__ C) {
    extern __shared__ __align__(1024) char smem[];
    const uint32_t sb = smem_u32(smem);

    const int tid  = threadIdx.x;
    const int warp = tid >> 5;
    const int lane = tid & 31;
    const int wm = (warp & 3) * 32;      // 4 m-warps
    const int wn = (warp >> 2) * 64;     // 4 n-warps

    const int m0 = blockIdx.y * BM;
    const int n0 = blockIdx.x * BN;

    // ---- producer addressing ----
    const int arow = tid >> 2;
    const int ach0 = (tid & 3) * 2;
    const __half* Ag = g_phi + (size_t)(m0 + arow) * KDIM + ach0 * 8;
    uint32_t Ad[2];
    #pragma unroll
    for (int j = 0; j < 2; j++) Ad[j] = sb + swz(arow, ach0 + j);
    const int brow = tid >> 1;
    const int bch0 = (tid & 1) * 4;
    const __half* Bg = g_w + (size_t)(n0 + brow) * KDIM + bch0 * 8;
    uint32_t Bd[4];
    #pragma unroll
    for (int j = 0; j < 4; j++) Bd[j] = sb + A_BYTES + swz(brow, bch0 + j);

    // ---- fragment addresses ----
    const int lA  = lane & 15;
    const int cA  = lane >> 4;
    const int lB  = (lane & 7) + ((lane >> 4) << 3);
    const int cB  = (lane >> 3) & 1;
    uint32_t aF[2], bF[4];
    #pragma unroll
    for (int mi = 0; mi < 2; mi++) {
        int r = wm + mi * 16 + lA;
        aF[mi] = (uint32_t)(r * 128 + ((r & 7) << 4));
    }
    #pragma unroll
    for (int j = 0; j < 4; j++) {
        int r = wn + j * 16 + lB;
        bF[j] = (uint32_t)(r * 128 + ((r & 7) << 4));
    }

    float acc[2][8][4];
    #pragma unroll
    for (int mi = 0; mi < 2; mi++)
        #pragma unroll
        for (int ni = 0; ni < 8; ni++)
            #pragma unroll
            for (int r = 0; r < 4; r++) acc[mi][ni][r] = 0.0f;

    // ---- prologue: stages 0..2 ----
    #pragma unroll
    for (int s = 0; s < 3; s++) {
        const uint32_t so = s * STAGE_BYTES;
        const int ko = s * BKH;
        #pragma unroll
        for (int j = 0; j < 2; j++) cp_async16(Ad[j] + so, Ag + ko + j * 8);
        #pragma unroll
        for (int j = 0; j < 4; j++) cp_async16(Bd[j] + so, Bg + ko + j * 8);
        asm volatile("cp.async.commit_group;\n");
    }

    for (int kt = 0; kt < KT; kt++) {
        if (kt < KT - 2)       asm volatile("cp.async.wait_group 2;\n");
        else if (kt == KT - 2) asm volatile("cp.async.wait_group 1;\n");
        else                   asm volatile("cp.async.wait_group 0;\n");
        __syncthreads();

        if (kt + 3 < KT) {
            const uint32_t so = ((kt + 3) % STAGES) * STAGE_BYTES;
            const int ko = (kt + 3) * BKH;
            #pragma unroll
            for (int j = 0; j < 2; j++) cp_async16(Ad[j] + so, Ag + ko + j * 8);
            #pragma unroll
            for (int j = 0; j < 4; j++) cp_async16(Bd[j] + so, Bg + ko + j * 8);
            asm volatile("cp.async.commit_group;\n");
        }

        const uint32_t stA = sb + (kt % STAGES) * STAGE_BYTES;
        const uint32_t stB = stA + A_BYTES;

        uint32_t a[2][4];                  // A frags, single-buffered
        uint32_t b[2][4][4];               // B frags, double-buffered

        // initial loads for ks = 0
        #pragma unroll
        for (int mi = 0; mi < 2; mi++)
            ldsm4(a[mi], (stA + aF[mi]) ^ (uint32_t)(cA << 4));
        #pragma unroll
        for (int j = 0; j < 4; j++)
            ldsm4(b[0][j], (stB + bF[j]) ^ (uint32_t)(cB << 4));

        #pragma unroll
        for (int ks = 0; ks < 4; ks++) {
            const int cur = ks & 1;
            // prefetch B frags for ks+1 BEFORE the MMA burst (overlaps)
            if (ks < 3) {
                const uint32_t kb = (uint32_t)((2 * (ks + 1) + cB) << 4);
                #pragma unroll
                for (int j = 0; j < 4; j++)
                    ldsm4(b[cur ^ 1][j], (stB + bF[j]) ^ kb);
            }
            // MMA burst (a current, b[cur] loaded previous step)
            #pragma unroll
            for (int mi = 0; mi < 2; mi++)
                #pragma unroll
                for (int ni = 0; ni < 8; ni++)
                    mma_f16(acc[mi][ni], a[mi], b[cur][ni >> 1][2 * (ni & 1)],
                                                 b[cur][ni >> 1][2 * (ni & 1) + 1]);
            // reload A frags for ks+1 after the burst consumed them
            if (ks < 3) {
                const uint32_t ka = (uint32_t)((2 * (ks + 1) + cA) << 4);
                #pragma unroll
                for (int mi = 0; mi < 2; mi++)
                    ldsm4(a[mi], (stA + aF[mi]) ^ ka);
            }
        }
    }

    // ---- epilogue ----
    const int g4 = lane >> 2;
    const int t4 = lane & 3;
    #pragma unroll
    for (int mi = 0; mi < 2; mi++) {
        const int row = m0 + wm + mi * 16 + g4;
        #pragma unroll
        for (int ni = 0; ni < 8; ni++) {
            const int col = n0 + wn + ni * 8 + t4 * 2;
            *reinterpret_cast<float2*>(C + (size_t)row * OUTF + col) =
                make_float2(acc[mi][ni][0], acc[mi][ni][1]);
            *reinterpret_cast<float2*>(C + (size_t)(row + 8) * OUTF + col) =
                make_float2(acc[mi][ni][2], acc[mi][ni][3]);
        }
    }
}

// pad launch: with order (w, phi, pad, gemm), ncu capture idx 15 -> gemm
__global__ void ncu_pad_kernel() {}

// ---------------------------------------------------------------------------
extern "C" void kernel_launch(void* const* d_in, const int* in_sizes, int n_in,
                              void* d_out, int out_size) {
    const float* x    = (const float*)d_in[0];   // (8192, 1024)
    const float* bw   = (const float*)d_in[1];   // (1024, 1024)
    const float* sw   = (const float*)d_in[2];   // (1024, 1024, 8)
    const float* sc   = (const float*)d_in[3];   // (1024, 1024)
    const float* grid = (const float*)d_in[4];   // (1024, 8)
    float* out = (float*)d_out;                  // (8192, 1024)

    (void)in_sizes; (void)n_in; (void)out_size;

    cudaFuncSetAttribute(gemm_f16_kernel,
                         cudaFuncAttributeMaxDynamicSharedMemorySize, SMEM_BYTES);

    prep_w_kernel<<<(OUTF * INF + 255) / 256, 256>>>(bw, sw, sc);
    prep_phi3_kernel<<<512, 256>>>(x, grid);
    ncu_pad_kernel<<<1, 32>>>();

    dim3 gdim(OUTF / BN, NTOK / BM);             // (4, 64) = 256 CTAs
    gemm_f16_kernel<<<gdim, 512, SMEM_BYTES>>>(out);
}

// round 17
// speedup vs baseline: 1.2683x; 1.2683x over previous
#include <cuda_runtime.h>
#include <cuda_fp16.h>
#include <cstdint>

// ---------------------------------------------------------------------------
// Problem constants
// ---------------------------------------------------------------------------
#define NTOK 8192
#define INF  1024
#define OUTF 1024
#define GS   8
#define KDIM (INF * 9)          // 9216 = silu + 8 laplacian features

static __device__ __align__(256) __half g_phi[(size_t)NTOK * KDIM];   // 151 MB
static __device__ __align__(256) __half g_w[(size_t)OUTF * KDIM];     // 18.9 MB

// ---------------------------------------------------------------------------
// prep_w (CLOCK CANARY: ~13.5us fast-DVFS / ~20.5us slow-DVFS)
// ---------------------------------------------------------------------------
__global__ void prep_w_kernel(const float* __restrict__ bw,
                              const float* __restrict__ sw,
                              const float* __restrict__ sc) {
    int idx = blockIdx.x * blockDim.x + threadIdx.x;
    if (idx >= OUTF * INF) return;
    int o = idx / INF;
    int i = idx - o * INF;
    size_t base = (size_t)o * KDIM + i;
    float scaler = sc[idx];
    g_w[base] = __float2half(bw[idx]);
    #pragma unroll
    for (int g = 0; g < GS; g++)
        g_w[base + (size_t)(1 + g) * INF] = __float2half(sw[(size_t)idx * GS + g] * scaler);
}

// ---------------------------------------------------------------------------
// prep_phi v3 (proven)
// ---------------------------------------------------------------------------
__device__ __forceinline__ void exp_pm(float xv, float& E, float& R) {
    const float L2E = 1.4426950408889634f;
    float s = xv * L2E;
    float k = s + 12582912.0f;
    int   n = __float_as_int(k) - 0x4B400000;
    float f = s - (k - 12582912.0f);
    float p = 1.33335581e-3f;
    p = fmaf(p, f, 9.61812910e-3f);
    p = fmaf(p, f, 5.55041087e-2f);
    p = fmaf(p, f, 2.40226507e-1f);
    p = fmaf(p, f, 6.93147181e-1f);
    p = fmaf(p, f, 1.0f);
    float nf = -f;
    float q = 1.33335581e-3f;
    q = fmaf(q, nf, 9.61812910e-3f);
    q = fmaf(q, nf, 5.55041087e-2f);
    q = fmaf(q, nf, 2.40226507e-1f);
    q = fmaf(q, nf, 6.93147181e-1f);
    q = fmaf(q, nf, 1.0f);
    E = p * __int_as_float((127 + n) << 23);
    R = q * __int_as_float((127 - n) << 23);
}

__device__ __forceinline__ float fast_sigmoid_from_R(float R) {
    float d = 1.0f + R;
    float y = __int_as_float(0x7EF477D5 - __float_as_int(d));
    y = y * (2.0f - d * y);
    y = y * (2.0f - d * y);
    y = y * (2.0f - d * y);
    return y;
}

__device__ __forceinline__ uint32_t pack2(float a, float b) {
    __half2 h = __floats2half2_rn(a, b);
    return *reinterpret_cast<uint32_t*>(&h);
}

__global__ void __launch_bounds__(256) prep_phi3_kernel(const float* __restrict__ x,
                                                        const float* __restrict__ gridp) {
    const int tid = threadIdx.x;
    const int i0 = tid * 4;
    const int n0 = blockIdx.x * 16;

    float cEv[4][GS], cRv[4][GS];
    #pragma unroll
    for (int e = 0; e < 4; e++)
        #pragma unroll
        for (int g = 0; g < GS; g++) {
            float gv = gridp[(i0 + e) * GS + g];
            cEv[e][g] = __expf(-gv);
            cRv[e][g] = __expf(gv);
        }

    for (int n = n0; n < n0 + 16; n++) {
        float4 xv = *reinterpret_cast<const float4*>(x + (size_t)n * INF + i0);
        float xa[4] = {xv.x, xv.y, xv.z, xv.w};
        float E[4], R[4], sil[4];
        #pragma unroll
        for (int e = 0; e < 4; e++) {
            exp_pm(xa[e], E[e], R[e]);
            sil[e] = xa[e] * fast_sigmoid_from_R(R[e]);
        }
        __half* base = g_phi + (size_t)n * KDIM + i0;
        uint2 u;
        u.x = pack2(sil[0], sil[1]);
        u.y = pack2(sil[2], sil[3]);
        *reinterpret_cast<uint2*>(base) = u;
        #pragma unroll
        for (int g = 0; g < GS; g++) {
            float v0 = fminf(E[0] * cEv[0][g], R[0] * cRv[0][g]);
            float v1 = fminf(E[1] * cEv[1][g], R[1] * cRv[1][g]);
            float v2 = fminf(E[2] * cEv[2][g], R[2] * cRv[2][g]);
            float v3 = fminf(E[3] * cEv[3][g], R[3] * cRv[3][g]);
            uint2 v;
            v.x = pack2(v0, v1);
            v.y = pack2(v2, v3);
            *reinterpret_cast<uint2*>(base + (size_t)(1 + g) * INF) = v;
        }
    }
}

// ---------------------------------------------------------------------------
// fp16 GEMM v9: mbarrier pipeline, FIXED (.noinc) + fill-2-ahead (2-iter
// warp drift slack). CTA 128x256x64h, 256 thr, 8 warps (2m x 4n, warp 64x64),
// 4 stages of 48 KB, double-buffered ldmatrix frags.
// ---------------------------------------------------------------------------
#define BM 128
#define BN 256
#define BKH 64
#define STAGES 4
#define A_BYTES (BM * 128)                 // 16 KB
#define B_BYTES (BN * 128)                 // 32 KB
#define STAGE_BYTES (A_BYTES + B_BYTES)    // 48 KB
#define DATA_BYTES (STAGES * STAGE_BYTES)  // 192 KB
#define MBAR_FULL(s)  (DATA_BYTES + (s) * 8)
#define MBAR_EMPTY(s) (DATA_BYTES + 32 + (s) * 8)
#define SMEM_BYTES    (DATA_BYTES + 64)
#define KT (KDIM / BKH)                    // 144

__device__ __forceinline__ void cp_async16(uint32_t smem_addr, const void* gptr) {
    asm volatile("cp.async.cg.shared.global [%0], [%1], 16;\n" :: "r"(smem_addr), "l"(gptr));
}
__device__ __forceinline__ uint32_t smem_u32(const void* p) {
    uint32_t a;
    asm("{ .reg .u64 t; cvta.to.shared.u64 t, %1; cvt.u32.u64 %0, t; }" : "=r"(a) : "l"(p));
    return a;
}
__device__ __forceinline__ void mbar_init(uint32_t addr, uint32_t count) {
    asm volatile("mbarrier.init.shared.b64 [%0], %1;" :: "r"(addr), "r"(count) : "memory");
}
__device__ __forceinline__ void mbar_arrive(uint32_t addr) {
    asm volatile("mbarrier.arrive.shared.b64 _, [%0];" :: "r"(addr) : "memory");
}
// FIXED: .noinc — default form increments pending count first (net-zero,
// phase never completes -> R14/15 deadlock).
__device__ __forceinline__ void cp_async_mbar_arrive(uint32_t addr) {
    asm volatile("cp.async.mbarrier.arrive.noinc.shared::cta.b64 [%0];"
                 :: "r"(addr) : "memory");
}
__device__ __forceinline__ void mbar_wait(uint32_t addr, uint32_t parity) {
    asm volatile(
        "{\n\t.reg .pred P;\n"
        "LW_%=:\n\t"
        "mbarrier.try_wait.parity.acquire.cta.shared::cta.b64 P, [%0], %1, 0x989680;\n\t"
        "@P bra LD_%=;\n\t"
        "bra LW_%=;\n"
        "LD_%=:\n\t}"
        :: "r"(addr), "r"(parity) : "memory");
}
__device__ __forceinline__ void ldsm4(uint32_t r[4], uint32_t addr) {
    asm volatile("ldmatrix.sync.aligned.m8n8.x4.shared.b16 {%0,%1,%2,%3}, [%4];"
                 : "=r"(r[0]), "=r"(r[1]), "=r"(r[2]), "=r"(r[3]) : "r"(addr));
}
__device__ __forceinline__ void mma_f16(float c[4], const uint32_t a[4],
                                        uint32_t b0, uint32_t b1) {
    asm volatile(
        "mma.sync.aligned.m16n8k16.row.col.f32.f16.f16.f32 "
        "{%0,%1,%2,%3}, {%4,%5,%6,%7}, {%8,%9}, {%0,%1,%2,%3};\n"
        : "+f"(c[0]), "+f"(c[1]), "+f"(c[2]), "+f"(c[3])
        : "r"(a[0]), "r"(a[1]), "r"(a[2]), "r"(a[3]), "r"(b0), "r"(b1));
}
__device__ __forceinline__ uint32_t swz(int row, int chunk) {
    return (uint32_t)(row * 128 + ((chunk ^ (row & 7)) << 4));
}

__global__ void __launch_bounds__(256, 1) gemm_f16_kernel(float* __restrict__ C) {
    extern __shared__ __align__(1024) char smem[];
    const uint32_t sb = smem_u32(smem);

    const int tid  = threadIdx.x;
    const int warp = tid >> 5;
    const int lane = tid & 31;
    const int wm = (warp & 1) * 64;
    const int wn = (warp >> 1) * 64;

    const int m0 = blockIdx.y * BM;
    const int n0 = blockIdx.x * BN;

    // ---- mbarrier init ----
    if (tid == 0) {
        #pragma unroll
        for (int s = 0; s < STAGES; s++) {
            mbar_init(sb + MBAR_FULL(s), 256);   // 256 noinc cp.async arrivals
            mbar_init(sb + MBAR_EMPTY(s), 8);    // one per warp
        }
    }
    __syncthreads();

    // ---- producer addressing ----
    const int crow = tid >> 1;
    const int cch0 = (tid & 1) * 4;
    const __half* Ag  = g_phi + (size_t)(m0 + crow) * KDIM + cch0 * 8;
    const __half* Bg0 = g_w   + (size_t)(n0 + crow) * KDIM + cch0 * 8;
    const __half* Bg1 = Bg0 + (size_t)128 * KDIM;
    uint32_t Ad[4];
    #pragma unroll
    for (int j = 0; j < 4; j++) Ad[j] = sb + swz(crow, cch0 + j);

    // ---- fragment addresses ----
    const int lA  = lane & 15;
    const int cA  = lane >> 4;
    const int lB  = (lane & 7) + ((lane >> 4) << 3);
    const int cB  = (lane >> 3) & 1;
    uint32_t aF[4], bF[4];
    #pragma unroll
    for (int mi = 0; mi < 4; mi++) {
        int r = wm + mi * 16 + lA;
        aF[mi] = (uint32_t)(r * 128 + ((r & 7) << 4));
    }
    #pragma unroll
    for (int j = 0; j < 4; j++) {
        int r = wn + j * 16 + lB;
        bF[j] = (uint32_t)(r * 128 + ((r & 7) << 4));
    }

    float acc[4][8][4];
    #pragma unroll
    for (int mi = 0; mi < 4; mi++)
        #pragma unroll
        for (int ni = 0; ni < 8; ni++)
            #pragma unroll
            for (int r = 0; r < 4; r++) acc[mi][ni][r] = 0.0f;

    auto fill = [&](int k) {
        const uint32_t so = (uint32_t)((k & 3) * STAGE_BYTES);
        const int ko = k * BKH;
        #pragma unroll
        for (int j = 0; j < 4; j++) {
            cp_async16(Ad[j] + so,                   Ag  + ko + j * 8);
            cp_async16(Ad[j] + so + A_BYTES,         Bg0 + ko + j * 8);
            cp_async16(Ad[j] + so + A_BYTES + 16384, Bg1 + ko + j * 8);
        }
        cp_async_mbar_arrive(sb + MBAR_FULL(k & 3));
    };

    // ---- prologue: fill stages 0,1 (fill distance = 2) ----
    fill(0);
    fill(1);

    const bool elect = (lane == 0);

    for (int kt = 0; kt < KT; kt++) {
        // prefetch stage kt+2 (its buffer consumed at kt-2 -> 2-iter slack)
        if (kt + 2 < KT) {
            if (kt >= 2)
                mbar_wait(sb + MBAR_EMPTY((kt + 2) & 3), (uint32_t)(((kt - 2) >> 2) & 1));
            fill(kt + 2);
        }

        // wait data for stage kt
        mbar_wait(sb + MBAR_FULL(kt & 3), (uint32_t)((kt >> 2) & 1));

        const uint32_t stA = sb + (uint32_t)((kt & 3) * STAGE_BYTES);
        const uint32_t stB = stA + A_BYTES;

        uint32_t a[2][4][4], b[2][4][4];

        // frags for ks=0
        #pragma unroll
        for (int mi = 0; mi < 4; mi++)
            ldsm4(a[0][mi], (stA + aF[mi]) ^ (uint32_t)(cA << 4));
        #pragma unroll
        for (int j = 0; j < 4; j++)
            ldsm4(b[0][j], (stB + bF[j]) ^ (uint32_t)(cB << 4));

        #pragma unroll
        for (int ks = 0; ks < 4; ks++) {
            const int cur = ks & 1;
            if (ks < 3) {                      // prefetch ks+1 before mma burst
                const int nxt = cur ^ 1;
                const uint32_t ka = (uint32_t)((2 * (ks + 1) + cA) << 4);
                const uint32_t kb = (uint32_t)((2 * (ks + 1) + cB) << 4);
                #pragma unroll
                for (int mi = 0; mi < 4; mi++) ldsm4(a[nxt][mi], (stA + aF[mi]) ^ ka);
                #pragma unroll
                for (int j = 0; j < 4; j++)    ldsm4(b[nxt][j], (stB + bF[j]) ^ kb);
            }
            #pragma unroll
            for (int mi = 0; mi < 4; mi++)
                #pragma unroll
                for (int ni = 0; ni < 8; ni++)
                    mma_f16(acc[mi][ni], a[cur][mi], b[cur][ni >> 1][2 * (ni & 1)],
                                                     b[cur][ni >> 1][2 * (ni & 1) + 1]);
        }

        // done reading stage kt (release: orders the ldsm reads above)
        if (elect) mbar_arrive(sb + MBAR_EMPTY(kt & 3));
    }

    // ---- epilogue ----
    const int g4 = lane >> 2;
    const int t4 = lane & 3;
    #pragma unroll
    for (int mi = 0; mi < 4; mi++) {
        const int row = m0 + wm + mi * 16 + g4;
        #pragma unroll
        for (int ni = 0; ni < 8; ni++) {
            const int col = n0 + wn + ni * 8 + t4 * 2;
            *reinterpret_cast<float2*>(C + (size_t)row * OUTF + col) =
                make_float2(acc[mi][ni][0], acc[mi][ni][1]);
            *reinterpret_cast<float2*>(C + (size_t)(row + 8) * OUTF + col) =
                make_float2(acc[mi][ni][2], acc[mi][ni][3]);
        }
    }
}

// pad launch: with order (w, phi, pad, gemm), ncu capture lands on gemm
__global__ void ncu_pad_kernel() {}

// ---------------------------------------------------------------------------
extern "C" void kernel_launch(void* const* d_in, const int* in_sizes, int n_in,
                              void* d_out, int out_size) {
    const float* x    = (const float*)d_in[0];   // (8192, 1024)
    const float* bw   = (const float*)d_in[1];   // (1024, 1024)
    const float* sw   = (const float*)d_in[2];   // (1024, 1024, 8)
    const float* sc   = (const float*)d_in[3];   // (1024, 1024)
    const float* grid = (const float*)d_in[4];   // (1024, 8)
    float* out = (float*)d_out;                  // (8192, 1024)

    (void)in_sizes; (void)n_in; (void)out_size;

    cudaFuncSetAttribute(gemm_f16_kernel,
                         cudaFuncAttributeMaxDynamicSharedMemorySize, SMEM_BYTES);

    prep_w_kernel<<<(OUTF * INF + 255) / 256, 256>>>(bw, sw, sc);
    prep_phi3_kernel<<<512, 256>>>(x, grid);
    ncu_pad_kernel<<<1, 32>>>();

    dim3 gdim(OUTF / BN, NTOK / BM);             // (4, 64) = 256 CTAs
    gemm_f16_kernel<<<gdim, 256, SMEM_BYTES>>>(out);
}